// round 16
// baseline (speedup 1.0000x reference)
#include <cuda_runtime.h>
#include <cuda_fp16.h>
#include <cstdint>

typedef unsigned int u32;

// ---- SMEM layout (byte offsets) ----
#define O_H    0         // u32 h[128][136]  f16x2 pairs, fragment-permuted, stride 136
#define O_XA   69632     // u32 xa[128][24]  compacted active-col activations
#define O_YE   81920     // float yE[128][34]
#define O_YO   99328     // float yO[128][34]
#define O_LDP  116736    // float ldp[128][4]
#define SMEM_REQ 118784

#define LN4Q 10240       // uint4 per (layer,net) weight block
__device__ __align__(256) uint4 g_wb[16 * LN4Q + 1024];  // +16KB pad for prefetch overrun

// ---------------- helpers ----------------
__device__ __forceinline__ float tanhf_(float x) {       // exact-ish (s-path only)
    float e = __expf(2.0f * x);
    return 1.0f - __fdividef(2.0f, e + 1.0f);
}
__device__ __forceinline__ float tanha(float x) {        // MUFU.TANH (h-path)
    float r;
    asm("tanh.approx.f32 %0, %1;" : "=f"(r) : "f"(x));
    return r;
}
__device__ __forceinline__ u32 h2pack(float a, float b) {
    __half2 h = __floats2half2_rn(a, b);
    return *(u32*)&h;
}
// fragment-permuted pair position: pair index pi -> u32 index within row
__device__ __host__ __forceinline__ int posperm(int pi) {
    return ((pi >> 3) << 3) + 2 * (pi & 3) + ((pi >> 2) & 1);
}
__device__ __forceinline__ void mma16816(float* d, u32 a0, u32 a1, u32 a2, u32 a3,
                                         u32 b0, u32 b1) {
    asm volatile(
        "mma.sync.aligned.m16n8k16.row.col.f32.f16.f16.f32 "
        "{%0,%1,%2,%3}, {%4,%5,%6,%7}, {%8,%9}, {%0,%1,%2,%3};"
        : "+f"(d[0]), "+f"(d[1]), "+f"(d[2]), "+f"(d[3])
        : "r"(a0), "r"(a1), "r"(a2), "r"(a3), "r"(b0), "r"(b1));
}
#define BARS() asm volatile("bar.sync %0, %1;" :: "r"(strip + 1), "r"(128) : "memory")

// ---------------- prep: pack fp16 weights into uint4 B-fragment layout ----------------
// Per (layer,net) block of LN4Q uint4:
//  G1 @0    : [2ks][16np][32lane]  uint4 = {frag(nt=2np), frag(nt=2np+1)}   (K=32 compacted)
//  G2 @1024 : [16ks][16np][32lane] same pairing (identity folded: W2' = W2 + I)
//  G3 @9216 : [8kp][4nt][32lane]   uint4 = {frag(ks=2kp), frag(ks=2kp+1)}   (N=32 compacted)
// frag uint2 = {f16x2(w0,w1), f16x2(w8,w9)}.
__device__ __forceinline__ uint2 mkfrag(int g, int layer, int net, int ks, int nt, int lane,
    const float* sW1, const float* sW2, const float* sW3,
    const float* tW1, const float* tW2, const float* tW3)
{
    float w0, w1, w8, w9;
    int n = nt * 8 + (lane >> 2);
    if (g == 0) {
        int par = layer & 1;
        const float* wr = (net ? tW1 : sW1) + (size_t)layer * 16384
                        + n * 64 + (ks * 16 + (lane & 3) * 2) * 2 + par;
        w0 = wr[0]; w1 = wr[2]; w8 = wr[16]; w9 = wr[18];
    } else if (g == 1) {
        int k = ks * 16 + (lane & 3) * 2;
        const float* wr = (net ? tW2 : sW2) + (size_t)layer * 65536 + (size_t)n * 256 + k;
        w0 = wr[0] + (n == k     ? 1.f : 0.f);
        w1 = wr[1] + (n == k + 1 ? 1.f : 0.f);
        w8 = wr[8] + (n == k + 8 ? 1.f : 0.f);
        w9 = wr[9] + (n == k + 9 ? 1.f : 0.f);
    } else {
        int op = (layer & 1) ^ 1;
        const float* wr = (net ? tW3 : sW3) + (size_t)layer * 16384
                        + (2 * n + op) * 256 + ks * 16 + (lane & 3) * 2;
        w0 = wr[0]; w1 = wr[1]; w8 = wr[8]; w9 = wr[9];
    }
    return make_uint2(h2pack(w0, w1), h2pack(w8, w9));
}

__global__ void prep(const float* __restrict__ sW1, const float* __restrict__ sW2,
                     const float* __restrict__ sW3, const float* __restrict__ tW1,
                     const float* __restrict__ tW2, const float* __restrict__ tW3)
{
    int t = blockIdx.x * blockDim.x + threadIdx.x;
    if (t >= 16 * LN4Q) return;
    int ln = t / LN4Q, rem = t % LN4Q;
    int layer = ln >> 1, net = ln & 1;
    uint2 f0, f1;
    if (rem < 1024) {                       // G1: pair n-tiles
        int ks = rem >> 9, np = (rem >> 5) & 15, lane = rem & 31;
        f0 = mkfrag(0, layer, net, ks, 2 * np,     lane, sW1, sW2, sW3, tW1, tW2, tW3);
        f1 = mkfrag(0, layer, net, ks, 2 * np + 1, lane, sW1, sW2, sW3, tW1, tW2, tW3);
    } else if (rem < 9216) {                // G2: pair n-tiles
        int q = rem - 1024;
        int ks = q >> 9, np = (q >> 5) & 15, lane = q & 31;
        f0 = mkfrag(1, layer, net, ks, 2 * np,     lane, sW1, sW2, sW3, tW1, tW2, tW3);
        f1 = mkfrag(1, layer, net, ks, 2 * np + 1, lane, sW1, sW2, sW3, tW1, tW2, tW3);
    } else {                                // G3: pair ks
        int q = rem - 9216;
        int kp = q >> 7, nt = (q >> 5) & 3, lane = q & 31;
        f0 = mkfrag(2, layer, net, 2 * kp,     nt, lane, sW1, sW2, sW3, tW1, tW2, tW3);
        f1 = mkfrag(2, layer, net, 2 * kp + 1, nt, lane, sW1, sW2, sW3, tW1, tW2, tW3);
    }
    g_wb[t] = make_uint4(f0.x, f0.y, f1.x, f1.y);
}

// ---------------- GEMM, M=32/warp, 8 n-tiles, ring-of-4 uint4 B pipeline ----------------
// bf[0..3] hold ALL 4 n-pairs of the current ks; each refill targets the same
// pair of ks+1 -> uniform full-iteration load-to-use distance.
template<int KS, int AST>
__device__ __forceinline__ void gemm8(float (&acc)[2][8][4],
                                      const uint4* __restrict__ Bw,
                                      uint4 (&bf)[4],
                                      const u32* __restrict__ Arow, int lane)
{
#pragma unroll
    for (int mt = 0; mt < 2; mt++)
#pragma unroll
        for (int j = 0; j < 8; j++)
#pragma unroll
            for (int i = 0; i < 4; i++) acc[mt][j][i] = 0.f;

    const u32* ap = Arow + (lane >> 2) * AST + 2 * (lane & 3);

#pragma unroll 1
    for (int ks = 0; ks < KS; ks++) {
        u32 A[2][4];
#pragma unroll
        for (int mt = 0; mt < 2; mt++) {
            const u32* p = ap + mt * (16 * AST) + ks * 8;
            uint2 v0 = *(const uint2*)p;              // a0, a2
            uint2 v1 = *(const uint2*)(p + 8 * AST);  // a1, a3
            A[mt][0] = v0.x; A[mt][2] = v0.y; A[mt][1] = v1.x; A[mt][3] = v1.y;
        }
        const uint4* bn = Bw + (ks + 1) * 512;        // ks+1 pairs (overrun -> adjacent valid region)
        uint4 b;
        b = bf[0]; bf[0] = bn[0];
        mma16816(acc[0][0], A[0][0], A[0][1], A[0][2], A[0][3], b.x, b.y);
        mma16816(acc[1][0], A[1][0], A[1][1], A[1][2], A[1][3], b.x, b.y);
        mma16816(acc[0][1], A[0][0], A[0][1], A[0][2], A[0][3], b.z, b.w);
        mma16816(acc[1][1], A[1][0], A[1][1], A[1][2], A[1][3], b.z, b.w);
        b = bf[1]; bf[1] = bn[32];
        mma16816(acc[0][2], A[0][0], A[0][1], A[0][2], A[0][3], b.x, b.y);
        mma16816(acc[1][2], A[1][0], A[1][1], A[1][2], A[1][3], b.x, b.y);
        mma16816(acc[0][3], A[0][0], A[0][1], A[0][2], A[0][3], b.z, b.w);
        mma16816(acc[1][3], A[1][0], A[1][1], A[1][2], A[1][3], b.z, b.w);
        b = bf[2]; bf[2] = bn[64];
        mma16816(acc[0][4], A[0][0], A[0][1], A[0][2], A[0][3], b.x, b.y);
        mma16816(acc[1][4], A[1][0], A[1][1], A[1][2], A[1][3], b.x, b.y);
        mma16816(acc[0][5], A[0][0], A[0][1], A[0][2], A[0][3], b.z, b.w);
        mma16816(acc[1][5], A[1][0], A[1][1], A[1][2], A[1][3], b.z, b.w);
        b = bf[3]; bf[3] = bn[96];
        mma16816(acc[0][6], A[0][0], A[0][1], A[0][2], A[0][3], b.x, b.y);
        mma16816(acc[1][6], A[1][0], A[1][1], A[1][2], A[1][3], b.x, b.y);
        mma16816(acc[0][7], A[0][0], A[0][1], A[0][2], A[0][3], b.z, b.w);
        mma16816(acc[1][7], A[1][0], A[1][1], A[1][2], A[1][3], b.z, b.w);
    }
}

// G3: M=32/warp, N=8 (one n-tile), K=256, ks-paired uint4 with depth-3 ring
__device__ __forceinline__ void gemm1(float (&a3)[2][4],
                                      const uint4* __restrict__ Bw,
                                      uint4 q0, uint4 q1, uint4 q2,
                                      const u32* __restrict__ Arow, int lane)
{
#pragma unroll
    for (int mt = 0; mt < 2; mt++)
#pragma unroll
        for (int i = 0; i < 4; i++) a3[mt][i] = 0.f;
    const u32* ap = Arow + (lane >> 2) * 136 + 2 * (lane & 3);
#pragma unroll
    for (int kp = 0; kp < 8; kp++) {
        uint4 b = q0; q0 = q1; q1 = q2; q2 = Bw[(kp + 3) * 128];
#pragma unroll
        for (int mt = 0; mt < 2; mt++) {
            const u32* p = ap + mt * (16 * 136) + kp * 16;
            uint2 v0 = *(const uint2*)p;
            uint2 v1 = *(const uint2*)(p + 8 * 136);
            mma16816(a3[mt], v0.x, v1.x, v0.y, v1.y, b.x, b.y);
            uint2 w0 = *(const uint2*)(p + 8);
            uint2 w1 = *(const uint2*)(p + 8 * 136 + 8);
            mma16816(a3[mt], w0.x, w1.x, w0.y, w1.y, b.z, b.w);
        }
    }
}

// epilogue for G1/G2: h = tanh.approx(D + bias) -> f16x2, fragment-permuted position
__device__ __forceinline__ void epi_h(float (&acc)[2][8][4],
                                      const float* __restrict__ biasg,
                                      u32* __restrict__ hB,
                                      int lane, int mprow, int nq)
{
#pragma unroll
    for (int j = 0; j < 8; j++) {
        int c2 = nq * 32 + j * 4 + (lane & 3);
        float2 bb = *(const float2*)(biasg + 2 * c2);
        int pos = posperm(c2);
#pragma unroll
        for (int mt = 0; mt < 2; mt++) {
            u32* p = hB + (mprow + mt * 16 + (lane >> 2)) * 136 + pos;
            p[0]       = h2pack(tanha(acc[mt][j][0] + bb.x), tanha(acc[mt][j][1] + bb.y));
            p[8 * 136] = h2pack(tanha(acc[mt][j][2] + bb.x), tanha(acc[mt][j][3] + bb.y));
        }
    }
}

// ---------------- main flow kernel ----------------
__global__ void __launch_bounds__(512, 1)
flow_kernel(const float* __restrict__ x,
            const float* __restrict__ sb1, const float* __restrict__ sb2,
            const float* __restrict__ sb3, const float* __restrict__ scale,
            const float* __restrict__ tb1, const float* __restrict__ tb2,
            const float* __restrict__ tb3,
            float* __restrict__ out, long long ld_off)
{
    extern __shared__ char smc[];
    u32*   hB  = (u32*)(smc + O_H);
    u32*   xaB = (u32*)(smc + O_XA);
    float* yE  = (float*)(smc + O_YE);
    float* yO  = (float*)(smc + O_YO);
    float* ldp = (float*)(smc + O_LDP);

    const int tid = threadIdx.x, lane = tid & 31, w = tid >> 5;
    const int strip = w >> 2, nq = w & 3, mprow = strip * 32;
    const long long gb = (long long)blockIdx.x * 128;

    {   // init: y split storage + compacted xa (layer 0 active = even cols)
        int r = tid >> 2, q = tid & 3;
        const float4* xr = (const float4*)(x + (gb + r) * 64) + q * 4;
#pragma unroll
        for (int i = 0; i < 4; i++) {
            float4 v = xr[i];
            int j = q * 8 + 2 * i;
            yE[r * 34 + j]     = v.x; yO[r * 34 + j]     = v.y;
            yE[r * 34 + j + 1] = v.z; yO[r * 34 + j + 1] = v.w;
            xaB[r * 24 + posperm(q * 4 + i)] = h2pack(v.x, v.z);
        }
    }
    __syncthreads();

    float ldacc[4] = {0.f, 0.f, 0.f, 0.f};   // per (mt, rr)
    float acc[2][8][4];
    float a3[2][4];
    float sreg[8];

#pragma unroll 1
    for (int layer = 0; layer < 8; layer++) {
        int op = (layer & 1) ^ 1;
#pragma unroll 1
        for (int net = 0; net < 2; net++) {
            const uint4* Wb = g_wb + (size_t)(layer * 2 + net) * LN4Q;
            const uint4* B1 = Wb + nq * 128 + lane;
            const uint4* B2 = Wb + 1024 + nq * 128 + lane;
            const uint4* B3 = Wb + 9216 + nq * 32 + lane;
            const float* b1g = (net ? tb1 : sb1) + layer * 256;
            const float* b2g = (net ? tb2 : sb2) + layer * 256;
            const float* b3g = (net ? tb3 : sb3) + layer * 64;

            uint4 bf[4];
            bf[0] = B1[0]; bf[1] = B1[32]; bf[2] = B1[64]; bf[3] = B1[96];
            BARS();
            gemm8<2, 24>(acc, B1, bf, xaB + mprow * 24, lane);
            bf[0] = B2[0]; bf[1] = B2[32]; bf[2] = B2[64]; bf[3] = B2[96];
            epi_h(acc, b1g, hB, lane, mprow, nq);
            BARS();
            gemm8<16, 136>(acc, B2, bf, hB + mprow * 136, lane);
            uint4 q0 = B3[0], q1 = B3[128], q2 = B3[256];  // G3 ring, hidden behind epi2+barrier
            BARS();
            epi_h(acc, b2g, hB, lane, mprow, nq);
            BARS();
            gemm1(a3, B3, q0, q1, q2, hB + mprow * 136, lane);

            int a = nq * 8 + (lane & 3) * 2;
            int c0 = 2 * a + op;
            float b30 = b3g[c0], b31 = b3g[c0 + 2];
            if (net == 0) {     // s-net: xm=0 at active-out dims -> s = tanh(D+b3)*sc (exact)
                const float* scg = scale + layer * 64;
                float sc0 = scg[c0], sc1 = scg[c0 + 2];
#pragma unroll
                for (int mt = 0; mt < 2; mt++)
#pragma unroll
                    for (int rr = 0; rr < 2; rr++) {
                        float s0 = tanhf_(a3[mt][rr * 2]     + b30) * sc0;
                        float s1 = tanhf_(a3[mt][rr * 2 + 1] + b31) * sc1;
                        sreg[mt * 4 + rr * 2]     = s0;
                        sreg[mt * 4 + rr * 2 + 1] = s1;
                        ldacc[mt * 2 + rr] += s0 + s1;
                    }
            } else {            // t-net: y2 = y*exp(s) + (D+b3); write y + next layer's xa
                float* yP = op ? yO : yE;
                int pos = posperm(nq * 4 + (lane & 3));
#pragma unroll
                for (int mt = 0; mt < 2; mt++)
#pragma unroll
                    for (int rr = 0; rr < 2; rr++) {
                        int r = mprow + mt * 16 + (lane >> 2) + rr * 8;
                        float2 yv = *(float2*)(yP + r * 34 + a);
                        float y0 = yv.x * __expf(sreg[mt * 4 + rr * 2])
                                 + a3[mt][rr * 2] + b30;
                        float y1 = yv.y * __expf(sreg[mt * 4 + rr * 2 + 1])
                                 + a3[mt][rr * 2 + 1] + b31;
                        *(float2*)(yP + r * 34 + a) = make_float2(y0, y1);
                        xaB[r * 24 + pos] = h2pack(y0, y1);
                    }
            }
        }
    }

#pragma unroll
    for (int k = 0; k < 4; k++) {
        ldacc[k] += __shfl_xor_sync(0xffffffffu, ldacc[k], 1);
        ldacc[k] += __shfl_xor_sync(0xffffffffu, ldacc[k], 2);
    }
    if ((lane & 3) == 0) {
#pragma unroll
        for (int k = 0; k < 4; k++) {
            int r = mprow + (k >> 1) * 16 + (lane >> 2) + (k & 1) * 8;
            ldp[r * 4 + nq] = ldacc[k];
        }
    }
    __syncthreads();
    {
        int r = tid >> 2, q = tid & 3;
        float4* orow = (float4*)(out + (gb + r) * 64) + q * 4;
#pragma unroll
        for (int i = 0; i < 4; i++) {
            int j = q * 8 + 2 * i;
            orow[i] = make_float4(yE[r * 34 + j], yO[r * 34 + j],
                                  yE[r * 34 + j + 1], yO[r * 34 + j + 1]);
        }
        if (tid < 128)
            out[ld_off + gb + tid] = ldp[tid * 4] + ldp[tid * 4 + 1]
                                   + ldp[tid * 4 + 2] + ldp[tid * 4 + 3];
    }
}

// ---------------- launch ----------------
extern "C" void kernel_launch(void* const* d_in, const int* in_sizes, int n_in,
                              void* d_out, int out_size)
{
    const float* x     = (const float*)d_in[0];
    const float* sW1   = (const float*)d_in[2];
    const float* sb1   = (const float*)d_in[3];
    const float* sW2   = (const float*)d_in[4];
    const float* sb2   = (const float*)d_in[5];
    const float* sW3   = (const float*)d_in[6];
    const float* sb3   = (const float*)d_in[7];
    const float* scale = (const float*)d_in[8];
    const float* tW1   = (const float*)d_in[9];
    const float* tb1   = (const float*)d_in[10];
    const float* tW2   = (const float*)d_in[11];
    const float* tb2   = (const float*)d_in[12];
    const float* tW3   = (const float*)d_in[13];
    const float* tb3   = (const float*)d_in[14];

    const int B = in_sizes[0] / 64;
    const long long ld_off = (long long)out_size - B;

    cudaFuncSetAttribute(flow_kernel, cudaFuncAttributeMaxDynamicSharedMemorySize,
                         SMEM_REQ);

    prep<<<640, 256>>>(sW1, sW2, sW3, tW1, tW2, tW3);
    flow_kernel<<<B / 128, 512, SMEM_REQ>>>(x, sb1, sb2, sb3, scale,
                                            tb1, tb2, tb3, (float*)d_out, ld_off);
}

// round 17
// speedup vs baseline: 1.0499x; 1.0499x over previous
#include <cuda_runtime.h>
#include <cuda_fp16.h>
#include <cstdint>

typedef unsigned int u32;

// ---- SMEM layout (byte offsets) ----
#define O_H1   0         // u32 h1[128][136]  G1 out / G2 in
#define O_H2   69632     // u32 h2[128][136]  G2 out / G3 in
#define O_XA   139264    // u32 xa[128][24]  compacted active-col activations
#define O_YE   151552    // float yE[128][34]
#define O_YO   168960    // float yO[128][34]
#define O_LDP  186368    // float ldp[128][4]
#define SMEM_REQ 188416

#define LN4Q 10240       // uint4 per (layer,net) weight block
__device__ __align__(256) uint4 g_wb[16 * LN4Q + 1024];  // +16KB pad for prefetch overrun

// ---------------- helpers ----------------
__device__ __forceinline__ float tanhf_(float x) {       // exact-ish (s-path only)
    float e = __expf(2.0f * x);
    return 1.0f - __fdividef(2.0f, e + 1.0f);
}
__device__ __forceinline__ float tanha(float x) {        // MUFU.TANH (h-path)
    float r;
    asm("tanh.approx.f32 %0, %1;" : "=f"(r) : "f"(x));
    return r;
}
__device__ __forceinline__ u32 h2pack(float a, float b) {
    __half2 h = __floats2half2_rn(a, b);
    return *(u32*)&h;
}
// fragment-permuted pair position: pair index pi -> u32 index within row
__device__ __host__ __forceinline__ int posperm(int pi) {
    return ((pi >> 3) << 3) + 2 * (pi & 3) + ((pi >> 2) & 1);
}
__device__ __forceinline__ void mma16816(float* d, u32 a0, u32 a1, u32 a2, u32 a3,
                                         u32 b0, u32 b1) {
    asm volatile(
        "mma.sync.aligned.m16n8k16.row.col.f32.f16.f16.f32 "
        "{%0,%1,%2,%3}, {%4,%5,%6,%7}, {%8,%9}, {%0,%1,%2,%3};"
        : "+f"(d[0]), "+f"(d[1]), "+f"(d[2]), "+f"(d[3])
        : "r"(a0), "r"(a1), "r"(a2), "r"(a3), "r"(b0), "r"(b1));
}
#define BARS() asm volatile("bar.sync %0, %1;" :: "r"(strip + 1), "r"(128) : "memory")

// ---------------- prep: pack fp16 weights into uint4 B-fragment layout ----------------
// Per (layer,net) block of LN4Q uint4:
//  G1 @0    : [2ks][16np][32lane]  uint4 = {frag(nt=2np), frag(nt=2np+1)}   (K=32 compacted)
//  G2 @1024 : [16ks][16np][32lane] same pairing (identity folded: W2' = W2 + I)
//  G3 @9216 : [8kp][4nt][32lane]   uint4 = {frag(ks=2kp), frag(ks=2kp+1)}   (N=32 compacted)
// frag uint2 = {f16x2(w0,w1), f16x2(w8,w9)}.
__device__ __forceinline__ uint2 mkfrag(int g, int layer, int net, int ks, int nt, int lane,
    const float* sW1, const float* sW2, const float* sW3,
    const float* tW1, const float* tW2, const float* tW3)
{
    float w0, w1, w8, w9;
    int n = nt * 8 + (lane >> 2);
    if (g == 0) {
        int par = layer & 1;
        const float* wr = (net ? tW1 : sW1) + (size_t)layer * 16384
                        + n * 64 + (ks * 16 + (lane & 3) * 2) * 2 + par;
        w0 = wr[0]; w1 = wr[2]; w8 = wr[16]; w9 = wr[18];
    } else if (g == 1) {
        int k = ks * 16 + (lane & 3) * 2;
        const float* wr = (net ? tW2 : sW2) + (size_t)layer * 65536 + (size_t)n * 256 + k;
        w0 = wr[0] + (n == k     ? 1.f : 0.f);
        w1 = wr[1] + (n == k + 1 ? 1.f : 0.f);
        w8 = wr[8] + (n == k + 8 ? 1.f : 0.f);
        w9 = wr[9] + (n == k + 9 ? 1.f : 0.f);
    } else {
        int op = (layer & 1) ^ 1;
        const float* wr = (net ? tW3 : sW3) + (size_t)layer * 16384
                        + (2 * n + op) * 256 + ks * 16 + (lane & 3) * 2;
        w0 = wr[0]; w1 = wr[1]; w8 = wr[8]; w9 = wr[9];
    }
    return make_uint2(h2pack(w0, w1), h2pack(w8, w9));
}

__global__ void prep(const float* __restrict__ sW1, const float* __restrict__ sW2,
                     const float* __restrict__ sW3, const float* __restrict__ tW1,
                     const float* __restrict__ tW2, const float* __restrict__ tW3)
{
    int t = blockIdx.x * blockDim.x + threadIdx.x;
    if (t >= 16 * LN4Q) return;
    int ln = t / LN4Q, rem = t % LN4Q;
    int layer = ln >> 1, net = ln & 1;
    uint2 f0, f1;
    if (rem < 1024) {                       // G1: pair n-tiles
        int ks = rem >> 9, np = (rem >> 5) & 15, lane = rem & 31;
        f0 = mkfrag(0, layer, net, ks, 2 * np,     lane, sW1, sW2, sW3, tW1, tW2, tW3);
        f1 = mkfrag(0, layer, net, ks, 2 * np + 1, lane, sW1, sW2, sW3, tW1, tW2, tW3);
    } else if (rem < 9216) {                // G2: pair n-tiles
        int q = rem - 1024;
        int ks = q >> 9, np = (q >> 5) & 15, lane = q & 31;
        f0 = mkfrag(1, layer, net, ks, 2 * np,     lane, sW1, sW2, sW3, tW1, tW2, tW3);
        f1 = mkfrag(1, layer, net, ks, 2 * np + 1, lane, sW1, sW2, sW3, tW1, tW2, tW3);
    } else {                                // G3: pair ks
        int q = rem - 9216;
        int kp = q >> 7, nt = (q >> 5) & 3, lane = q & 31;
        f0 = mkfrag(2, layer, net, 2 * kp,     nt, lane, sW1, sW2, sW3, tW1, tW2, tW3);
        f1 = mkfrag(2, layer, net, 2 * kp + 1, nt, lane, sW1, sW2, sW3, tW1, tW2, tW3);
    }
    g_wb[t] = make_uint4(f0.x, f0.y, f1.x, f1.y);
}

// ---------------- GEMM, M=32/warp, 8 n-tiles, uint4 B streamed JIT (R14 schedule) ----------------
template<int KS, int AST>
__device__ __forceinline__ void gemm8(float (&acc)[2][8][4],
                                      const uint4* __restrict__ Bw,
                                      uint4 bf0, uint4 bf1,
                                      const u32* __restrict__ Arow, int lane)
{
#pragma unroll
    for (int mt = 0; mt < 2; mt++)
#pragma unroll
        for (int j = 0; j < 8; j++)
#pragma unroll
            for (int i = 0; i < 4; i++) acc[mt][j][i] = 0.f;

    const u32* ap = Arow + (lane >> 2) * AST + 2 * (lane & 3);

#pragma unroll 1
    for (int ks = 0; ks < KS; ks++) {
        u32 A[2][4];
#pragma unroll
        for (int mt = 0; mt < 2; mt++) {
            const u32* p = ap + mt * (16 * AST) + ks * 8;
            uint2 v0 = *(const uint2*)p;              // a0, a2
            uint2 v1 = *(const uint2*)(p + 8 * AST);  // a1, a3
            A[mt][0] = v0.x; A[mt][2] = v0.y; A[mt][1] = v1.x; A[mt][3] = v1.y;
        }
        const uint4* bq = Bw + ks * 512;
        uint4 b;
        b = bf0; bf0 = bq[64];                       // refill pair2 (tiles 4,5)
        mma16816(acc[0][0], A[0][0], A[0][1], A[0][2], A[0][3], b.x, b.y);
        mma16816(acc[1][0], A[1][0], A[1][1], A[1][2], A[1][3], b.x, b.y);
        mma16816(acc[0][1], A[0][0], A[0][1], A[0][2], A[0][3], b.z, b.w);
        mma16816(acc[1][1], A[1][0], A[1][1], A[1][2], A[1][3], b.z, b.w);
        b = bf1; bf1 = bq[96];                       // refill pair3 (tiles 6,7)
        mma16816(acc[0][2], A[0][0], A[0][1], A[0][2], A[0][3], b.x, b.y);
        mma16816(acc[1][2], A[1][0], A[1][1], A[1][2], A[1][3], b.x, b.y);
        mma16816(acc[0][3], A[0][0], A[0][1], A[0][2], A[0][3], b.z, b.w);
        mma16816(acc[1][3], A[1][0], A[1][1], A[1][2], A[1][3], b.z, b.w);
        b = bf0; bf0 = bq[512];                      // refill ks+1 pair0 (overrun -> next region, valid)
        mma16816(acc[0][4], A[0][0], A[0][1], A[0][2], A[0][3], b.x, b.y);
        mma16816(acc[1][4], A[1][0], A[1][1], A[1][2], A[1][3], b.x, b.y);
        mma16816(acc[0][5], A[0][0], A[0][1], A[0][2], A[0][3], b.z, b.w);
        mma16816(acc[1][5], A[1][0], A[1][1], A[1][2], A[1][3], b.z, b.w);
        b = bf1; bf1 = bq[512 + 32];                 // refill ks+1 pair1
        mma16816(acc[0][6], A[0][0], A[0][1], A[0][2], A[0][3], b.x, b.y);
        mma16816(acc[1][6], A[1][0], A[1][1], A[1][2], A[1][3], b.x, b.y);
        mma16816(acc[0][7], A[0][0], A[0][1], A[0][2], A[0][3], b.z, b.w);
        mma16816(acc[1][7], A[1][0], A[1][1], A[1][2], A[1][3], b.z, b.w);
    }
}

// G3: M=32/warp, N=8 (one n-tile), K=256, ks-paired uint4 with depth-3 ring
__device__ __forceinline__ void gemm1(float (&a3)[2][4],
                                      const uint4* __restrict__ Bw,
                                      uint4 q0, uint4 q1, uint4 q2,
                                      const u32* __restrict__ Arow, int lane)
{
#pragma unroll
    for (int mt = 0; mt < 2; mt++)
#pragma unroll
        for (int i = 0; i < 4; i++) a3[mt][i] = 0.f;
    const u32* ap = Arow + (lane >> 2) * 136 + 2 * (lane & 3);
#pragma unroll
    for (int kp = 0; kp < 8; kp++) {
        uint4 b = q0; q0 = q1; q1 = q2; q2 = Bw[(kp + 3) * 128];
#pragma unroll
        for (int mt = 0; mt < 2; mt++) {
            const u32* p = ap + mt * (16 * 136) + kp * 16;
            uint2 v0 = *(const uint2*)p;
            uint2 v1 = *(const uint2*)(p + 8 * 136);
            mma16816(a3[mt], v0.x, v1.x, v0.y, v1.y, b.x, b.y);
            uint2 w0 = *(const uint2*)(p + 8);
            uint2 w1 = *(const uint2*)(p + 8 * 136 + 8);
            mma16816(a3[mt], w0.x, w1.x, w0.y, w1.y, b.z, b.w);
        }
    }
}

// epilogue for G1/G2: h = tanh.approx(D + bias) -> f16x2, fragment-permuted position
__device__ __forceinline__ void epi_h(float (&acc)[2][8][4],
                                      const float* __restrict__ biasg,
                                      u32* __restrict__ hOut,
                                      int lane, int mprow, int nq)
{
#pragma unroll
    for (int j = 0; j < 8; j++) {
        int c2 = nq * 32 + j * 4 + (lane & 3);
        float2 bb = *(const float2*)(biasg + 2 * c2);
        int pos = posperm(c2);
#pragma unroll
        for (int mt = 0; mt < 2; mt++) {
            u32* p = hOut + (mprow + mt * 16 + (lane >> 2)) * 136 + pos;
            p[0]       = h2pack(tanha(acc[mt][j][0] + bb.x), tanha(acc[mt][j][1] + bb.y));
            p[8 * 136] = h2pack(tanha(acc[mt][j][2] + bb.x), tanha(acc[mt][j][3] + bb.y));
        }
    }
}

// ---------------- main flow kernel ----------------
__global__ void __launch_bounds__(512, 1)
flow_kernel(const float* __restrict__ x,
            const float* __restrict__ sb1, const float* __restrict__ sb2,
            const float* __restrict__ sb3, const float* __restrict__ scale,
            const float* __restrict__ tb1, const float* __restrict__ tb2,
            const float* __restrict__ tb3,
            float* __restrict__ out, long long ld_off)
{
    extern __shared__ char smc[];
    u32*   h1B = (u32*)(smc + O_H1);
    u32*   h2B = (u32*)(smc + O_H2);
    u32*   xaB = (u32*)(smc + O_XA);
    float* yE  = (float*)(smc + O_YE);
    float* yO  = (float*)(smc + O_YO);
    float* ldp = (float*)(smc + O_LDP);

    const int tid = threadIdx.x, lane = tid & 31, w = tid >> 5;
    const int strip = w >> 2, nq = w & 3, mprow = strip * 32;
    const long long gb = (long long)blockIdx.x * 128;

    {   // init: y split storage + compacted xa (layer 0 active = even cols)
        int r = tid >> 2, q = tid & 3;
        const float4* xr = (const float4*)(x + (gb + r) * 64) + q * 4;
#pragma unroll
        for (int i = 0; i < 4; i++) {
            float4 v = xr[i];
            int j = q * 8 + 2 * i;
            yE[r * 34 + j]     = v.x; yO[r * 34 + j]     = v.y;
            yE[r * 34 + j + 1] = v.z; yO[r * 34 + j + 1] = v.w;
            xaB[r * 24 + posperm(q * 4 + i)] = h2pack(v.x, v.z);
        }
    }
    __syncthreads();

    float ldacc[4] = {0.f, 0.f, 0.f, 0.f};   // per (mt, rr)
    float acc[2][8][4];
    float a3[2][4];
    float sreg[8];

#pragma unroll 1
    for (int layer = 0; layer < 8; layer++) {
        int op = (layer & 1) ^ 1;
#pragma unroll 1
        for (int net = 0; net < 2; net++) {
            const uint4* Wb = g_wb + (size_t)(layer * 2 + net) * LN4Q;
            const uint4* B1 = Wb + nq * 128 + lane;
            const uint4* B2 = Wb + 1024 + nq * 128 + lane;
            const uint4* B3 = Wb + 9216 + nq * 32 + lane;
            const float* b1g = (net ? tb1 : sb1) + layer * 256;
            const float* b2g = (net ? tb2 : sb2) + layer * 256;
            const float* b3g = (net ? tb3 : sb3) + layer * 64;

            uint4 p10 = B1[0], p11 = B1[32];        // G1 initial B, hidden behind barrier
            BARS();                                  // xa ready (prev t-epi done)
            gemm8<2, 24>(acc, B1, p10, p11, xaB + mprow * 24, lane);
            uint4 p20 = B2[0], p21 = B2[32];        // G2 initial B, hidden behind epi1+barrier
            epi_h(acc, b1g, h1B, lane, mprow, nq);  // -> h1
            BARS();                                  // h1 ready
            gemm8<16, 136>(acc, B2, p20, p21, h1B + mprow * 136, lane);
            uint4 q0 = B3[0], q1 = B3[128], q2 = B3[256];  // G3 ring, hidden behind epi2
            epi_h(acc, b2g, h2B, lane, mprow, nq);  // -> h2 (no barrier: fresh buffer)
            BARS();                                  // h2 ready
            gemm1(a3, B3, q0, q1, q2, h2B + mprow * 136, lane);

            int a = nq * 8 + (lane & 3) * 2;
            int c0 = 2 * a + op;
            float b30 = b3g[c0], b31 = b3g[c0 + 2];
            if (net == 0) {     // s-net: xm=0 at active-out dims -> s = tanh(D+b3)*sc (exact)
                const float* scg = scale + layer * 64;
                float sc0 = scg[c0], sc1 = scg[c0 + 2];
#pragma unroll
                for (int mt = 0; mt < 2; mt++)
#pragma unroll
                    for (int rr = 0; rr < 2; rr++) {
                        float s0 = tanhf_(a3[mt][rr * 2]     + b30) * sc0;
                        float s1 = tanhf_(a3[mt][rr * 2 + 1] + b31) * sc1;
                        sreg[mt * 4 + rr * 2]     = s0;
                        sreg[mt * 4 + rr * 2 + 1] = s1;
                        ldacc[mt * 2 + rr] += s0 + s1;
                    }
            } else {            // t-net: y2 = y*exp(s) + (D+b3); write y + next layer's xa
                float* yP = op ? yO : yE;
                int pos = posperm(nq * 4 + (lane & 3));
#pragma unroll
                for (int mt = 0; mt < 2; mt++)
#pragma unroll
                    for (int rr = 0; rr < 2; rr++) {
                        int r = mprow + mt * 16 + (lane >> 2) + rr * 8;
                        float2 yv = *(float2*)(yP + r * 34 + a);
                        float y0 = yv.x * __expf(sreg[mt * 4 + rr * 2])
                                 + a3[mt][rr * 2] + b30;
                        float y1 = yv.y * __expf(sreg[mt * 4 + rr * 2 + 1])
                                 + a3[mt][rr * 2 + 1] + b31;
                        *(float2*)(yP + r * 34 + a) = make_float2(y0, y1);
                        xaB[r * 24 + pos] = h2pack(y0, y1);
                    }
            }
        }
    }

#pragma unroll
    for (int k = 0; k < 4; k++) {
        ldacc[k] += __shfl_xor_sync(0xffffffffu, ldacc[k], 1);
        ldacc[k] += __shfl_xor_sync(0xffffffffu, ldacc[k], 2);
    }
    if ((lane & 3) == 0) {
#pragma unroll
        for (int k = 0; k < 4; k++) {
            int r = mprow + (k >> 1) * 16 + (lane >> 2) + (k & 1) * 8;
            ldp[r * 4 + nq] = ldacc[k];
        }
    }
    __syncthreads();
    {
        int r = tid >> 2, q = tid & 3;
        float4* orow = (float4*)(out + (gb + r) * 64) + q * 4;
#pragma unroll
        for (int i = 0; i < 4; i++) {
            int j = q * 8 + 2 * i;
            orow[i] = make_float4(yE[r * 34 + j], yO[r * 34 + j],
                                  yE[r * 34 + j + 1], yO[r * 34 + j + 1]);
        }
        if (tid < 128)
            out[ld_off + gb + tid] = ldp[tid * 4] + ldp[tid * 4 + 1]
                                   + ldp[tid * 4 + 2] + ldp[tid * 4 + 3];
    }
}

// ---------------- launch ----------------
extern "C" void kernel_launch(void* const* d_in, const int* in_sizes, int n_in,
                              void* d_out, int out_size)
{
    const float* x     = (const float*)d_in[0];
    const float* sW1   = (const float*)d_in[2];
    const float* sb1   = (const float*)d_in[3];
    const float* sW2   = (const float*)d_in[4];
    const float* sb2   = (const float*)d_in[5];
    const float* sW3   = (const float*)d_in[6];
    const float* sb3   = (const float*)d_in[7];
    const float* scale = (const float*)d_in[8];
    const float* tW1   = (const float*)d_in[9];
    const float* tb1   = (const float*)d_in[10];
    const float* tW2   = (const float*)d_in[11];
    const float* tb2   = (const float*)d_in[12];
    const float* tW3   = (const float*)d_in[13];
    const float* tb3   = (const float*)d_in[14];

    const int B = in_sizes[0] / 64;
    const long long ld_off = (long long)out_size - B;

    cudaFuncSetAttribute(flow_kernel, cudaFuncAttributeMaxDynamicSharedMemorySize,
                         SMEM_REQ);

    prep<<<640, 256>>>(sW1, sW2, sW3, tW1, tW2, tW3);
    flow_kernel<<<B / 128, 512, SMEM_REQ>>>(x, sb1, sb2, sb3, scale,
                                            tb1, tb2, tb3, (float*)d_out, ld_off);
}